// round 13
// baseline (speedup 1.0000x reference)
#include <cuda_runtime.h>
#include <cuda_fp16.h>
#include <math.h>

// Problem constants (fixed by the dataset)
#define NN   50000
#define EEDG 600000
#define DD   128
#define EDIM 16
#define ENMAX (EEDG + NN)

// ---------------- device scratch (no allocations allowed) ----------------
__device__ int   g_is64;
__device__ int   g_cnt[NN];
__device__ int   g_off[NN + 1];
__device__ int   g_cur[NN];
__device__ int   g_part[128];
__device__ int2  g_es[ENMAX];          // (eid, src) in CSR-by-dst order
__device__ float g_loop[NN * EDIM];
__device__ float g_h[(size_t)NN * DD];
__device__ float g_xl[(size_t)NN * DD];
__device__ float g_xr[(size_t)NN * DD];
__device__ float g_wc[2 * DD * DD];    // composed layer-0 weights
__device__ float g_bc[2 * DD];         // composed layer-0 biases
__device__ __half g_ee[(size_t)ENMAX * DD];   // per-CSR-position edge features (166 MB)

// edge_index may arrive as int32 (jax x64 disabled) or int64. Detect on device.
__device__ __forceinline__ int eidx(const void* ei, long long i) {
    if (g_is64) return (int)((const long long*)ei)[i];
    return ((const int*)ei)[i];
}

__global__ void k_detect(const int* ei32) {
    __shared__ int s_any;
    if (threadIdx.x == 0) s_any = 0;
    __syncthreads();
    int v = ei32[2 * threadIdx.x + 1];
    if (v != 0) atomicOr(&s_any, 1);
    __syncthreads();
    if (threadIdx.x == 0) g_is64 = (s_any == 0);
}

__global__ void k_zero(int n) {
    int i = blockIdx.x * blockDim.x + threadIdx.x;
    if (i < n) g_cnt[i] = 0;
}

__global__ void k_hist(const void* ei, int E) {
    int e = blockIdx.x * blockDim.x + threadIdx.x;
    if (e < E) {
        int d = eidx(ei, (long long)E + e);
        atomicAdd(&g_cnt[d], 1);
    }
}

// ---- 3-phase scan of (cnt[i]+1) -> g_off (exclusive offsets), g_cur ----
__global__ void k_scan1(int n) {
    __shared__ int wsum[32];
    int tid = threadIdx.x, lane = tid & 31, wid = tid >> 5;
    int i = blockIdx.x * 1024 + tid;
    int v = (i < n) ? (g_cnt[i] + 1) : 0;
    int s = v;
    #pragma unroll
    for (int o = 1; o < 32; o <<= 1) {
        int t = __shfl_up_sync(0xffffffffu, s, o);
        if (lane >= o) s += t;
    }
    if (lane == 31) wsum[wid] = s;
    __syncthreads();
    if (wid == 0) {
        int ws = wsum[lane];
        #pragma unroll
        for (int o = 1; o < 32; o <<= 1) {
            int t = __shfl_up_sync(0xffffffffu, ws, o);
            if (lane >= o) ws += t;
        }
        wsum[lane] = ws;
    }
    __syncthreads();
    int incl = s + (wid ? wsum[wid - 1] : 0);
    if (i < n) g_off[i + 1] = incl;
    if (tid == 1023) g_part[blockIdx.x] = incl;
}

__global__ void k_scan2(int nb) {
    __shared__ int s[128];
    int t = threadIdx.x;
    int v = (t < nb) ? g_part[t] : 0;
    s[t] = v;
    __syncthreads();
    for (int o = 1; o < 128; o <<= 1) {
        int x = (t >= o) ? s[t - o] : 0;
        __syncthreads();
        s[t] += x;
        __syncthreads();
    }
    if (t < nb) g_part[t] = s[t];
}

__global__ void k_scan3(int n) {
    int i = blockIdx.x * blockDim.x + threadIdx.x;
    if (i == 0) g_off[0] = 0;
    if (i < n) {
        int b = i >> 10;
        int carry = (b > 0) ? g_part[b - 1] : 0;
        int off = g_off[i + 1] + carry;
        g_off[i + 1] = off;
        g_cur[i] = off - (g_cnt[i] + 1);
    }
}

__global__ void k_fill(const void* ei, int E, int EN) {
    int e = blockIdx.x * blockDim.x + threadIdx.x;
    if (e < EN) {
        int d, s;
        if (e < E) {
            d = eidx(ei, (long long)E + e);
            s = eidx(ei, e);
        } else {
            d = e - E;
            s = e - E;
        }
        int p = atomicAdd(&g_cur[d], 1);
        g_es[p] = make_int2(e, s);
    }
}

// loop_attr[i] = mean of incoming (real) edge_attr
__global__ void k_loopattr(const float* __restrict__ ea, int E, int N) {
    int w = blockIdx.x * (blockDim.x >> 5) + (threadIdx.x >> 5);
    int lane = threadIdx.x & 31;
    if (w >= N) return;
    int beg = g_off[w], end = g_off[w + 1];
    if (lane < 16) {
        float s = 0.f;
        for (int j = beg; j < end; j++) {
            int eid = g_es[j].x;
            if (eid < E) s += ea[(size_t)eid * 16 + lane];
        }
        float deg = (float)(end - beg - 1);
        g_loop[w * 16 + lane] = s / fmaxf(deg, 1.0f);
    }
}

// ---- compose layer-0 weights: g_wc[y] = in_w @ W, g_bc[y] = in_b @ W + b ----
__global__ void k_combine(const float* __restrict__ in_w, const float* __restrict__ in_b,
                          const float* __restrict__ Wl, const float* __restrict__ bl,
                          const float* __restrict__ Wr, const float* __restrict__ br)
{
    const float* W = blockIdx.y ? Wr : Wl;
    const float* bb = blockIdx.y ? br : bl;
    __shared__ float srow[128];
    int col = threadIdx.x;
    int row = blockIdx.x;
    srow[col] = in_w[row * 128 + col];
    __syncthreads();
    float s = 0.f;
    for (int k = 0; k < 128; k++) s += srow[k] * W[k * 128 + col];
    g_wc[blockIdx.y * 128 * 128 + row * 128 + col] = s;
    if (row == 0) {
        float t = bb[col];
        for (int k = 0; k < 128; k++) t += in_b[k] * W[k * 128 + col];
        g_bc[blockIdx.y * 128 + col] = t;
    }
}

// ---------------- tf32 helpers ----------------
__device__ __forceinline__ unsigned f2tf32(float f) {
    unsigned r;
    asm("cvt.rna.tf32.f32 %0, %1;" : "=r"(r) : "f"(f));
    return r;
}

// ---------------- tf32 tensor-core GEMM: C[M,128] = A[M,128] @ B[128,128] + bias ----------------
__global__ void __launch_bounds__(256) mma_gemm(
    const float* __restrict__ A_in,
    const float* __restrict__ B0, const float* __restrict__ bias0, int bsel0, int dst0,
    const float* __restrict__ B1, const float* __restrict__ bias1, int bsel1, int dst1,
    int M)
{
    const float* A = (A_in != nullptr) ? A_in : (const float*)g_h;
    const float* B;
    const float* bias;
    int dst;
    if (blockIdx.y) {
        B = (bsel1 >= 0) ? (const float*)(g_wc + bsel1 * 128 * 128) : B1;
        bias = (bsel1 >= 0) ? (const float*)(g_bc + bsel1 * 128) : bias1;
        dst = dst1;
    } else {
        B = (bsel0 >= 0) ? (const float*)(g_wc + bsel0 * 128 * 128) : B0;
        bias = (bsel0 >= 0) ? (const float*)(g_bc + bsel0 * 128) : bias0;
        dst = dst0;
    }
    float* C = (dst == 0) ? g_h : (dst == 1) ? g_xl : g_xr;

    __shared__ unsigned As[128][36];
    __shared__ unsigned Bs[32][136];

    const int tid = threadIdx.x;
    const int lane = tid & 31;
    const int wid = tid >> 5;
    const int wm = wid >> 1;
    const int wn = wid & 1;
    const int g  = lane >> 2;
    const int tg = lane & 3;
    const int rowBase = blockIdx.x * 128;

    float c[2][8][4];
    #pragma unroll
    for (int mt = 0; mt < 2; mt++)
        #pragma unroll
        for (int nt = 0; nt < 8; nt++)
            #pragma unroll
            for (int q = 0; q < 4; q++) c[mt][nt][q] = 0.f;

    for (int k0 = 0; k0 < 128; k0 += 32) {
        #pragma unroll
        for (int it = 0; it < 4; it++) {
            int linear = tid + it * 256;
            int r  = linear >> 3;
            int c4 = (linear & 7) * 4;
            float4 v = make_float4(0.f, 0.f, 0.f, 0.f);
            int row = rowBase + r;
            if (row < M) v = *(const float4*)(A + (size_t)row * 128 + k0 + c4);
            As[r][c4 + 0] = f2tf32(v.x);
            As[r][c4 + 1] = f2tf32(v.y);
            As[r][c4 + 2] = f2tf32(v.z);
            As[r][c4 + 3] = f2tf32(v.w);

            int rb  = linear >> 5;
            int cb4 = (linear & 31) * 4;
            float4 bv = *(const float4*)(B + (size_t)(k0 + rb) * 128 + cb4);
            Bs[rb][cb4 + 0] = f2tf32(bv.x);
            Bs[rb][cb4 + 1] = f2tf32(bv.y);
            Bs[rb][cb4 + 2] = f2tf32(bv.z);
            Bs[rb][cb4 + 3] = f2tf32(bv.w);
        }
        __syncthreads();

        #pragma unroll
        for (int ks = 0; ks < 4; ks++) {
            int k8 = ks * 8;
            unsigned a[2][4];
            #pragma unroll
            for (int mt = 0; mt < 2; mt++) {
                int r0 = wm * 32 + mt * 16 + g;
                a[mt][0] = As[r0    ][k8 + tg];
                a[mt][1] = As[r0 + 8][k8 + tg];
                a[mt][2] = As[r0    ][k8 + tg + 4];
                a[mt][3] = As[r0 + 8][k8 + tg + 4];
            }
            unsigned b[8][2];
            #pragma unroll
            for (int nt = 0; nt < 8; nt++) {
                int col = wn * 64 + nt * 8 + g;
                b[nt][0] = Bs[k8 + tg    ][col];
                b[nt][1] = Bs[k8 + tg + 4][col];
            }
            #pragma unroll
            for (int mt = 0; mt < 2; mt++)
                #pragma unroll
                for (int nt = 0; nt < 8; nt++) {
                    asm volatile(
                        "mma.sync.aligned.m16n8k8.row.col.f32.tf32.tf32.f32 "
                        "{%0,%1,%2,%3}, {%4,%5,%6,%7}, {%8,%9}, {%0,%1,%2,%3};"
                        : "+f"(c[mt][nt][0]), "+f"(c[mt][nt][1]),
                          "+f"(c[mt][nt][2]), "+f"(c[mt][nt][3])
                        : "r"(a[mt][0]), "r"(a[mt][1]), "r"(a[mt][2]), "r"(a[mt][3]),
                          "r"(b[nt][0]), "r"(b[nt][1]));
                }
        }
        __syncthreads();
    }

    #pragma unroll
    for (int mt = 0; mt < 2; mt++) {
        int row0 = rowBase + wm * 32 + mt * 16 + g;
        #pragma unroll
        for (int nt = 0; nt < 8; nt++) {
            int col = wn * 64 + nt * 8 + 2 * tg;
            float b0 = bias[col], b1 = bias[col + 1];
            if (row0 < M) {
                float2 o = make_float2(c[mt][nt][0] + b0, c[mt][nt][1] + b1);
                *(float2*)(C + (size_t)row0 * 128 + col) = o;
            }
            int row1 = row0 + 8;
            if (row1 < M) {
                float2 o = make_float2(c[mt][nt][2] + b0, c[mt][nt][3] + b1);
                *(float2*)(C + (size_t)row1 * 128 + col) = o;
            }
        }
    }
}

// ---------------- ee GEMM: g_ee[pos][c] = sum_k ea_row(g_es[pos].x)[k] * We[k][c] ----------------
// 128 CSR positions x 128 cols per block, K=16, tf32 mma, fp16 output in CSR order.
__global__ void __launch_bounds__(256) k_eegemm(
    const float* __restrict__ ea, const float* __restrict__ We, int E, int EN)
{
    __shared__ unsigned As[128][20];   // stride 20: conflict-free frag reads
    __shared__ unsigned Bs[16][136];
    int tid = threadIdx.x;
    int base = blockIdx.x * 128;

    {   // A tile: 128 rows x 16 k (gather by CSR eid)
        int r = tid >> 1, hf = tid & 1;
        int pos = base + r;
        float4 v0 = make_float4(0.f, 0.f, 0.f, 0.f);
        float4 v1 = v0;
        if (pos < EN) {
            int eid = g_es[pos].x;
            const float* p = (eid < E) ? (ea + (size_t)eid * 16)
                                       : (g_loop + (size_t)(eid - E) * 16);
            v0 = *(const float4*)(p + hf * 8);
            v1 = *(const float4*)(p + hf * 8 + 4);
        }
        int cb = hf * 8;
        As[r][cb + 0] = f2tf32(v0.x);
        As[r][cb + 1] = f2tf32(v0.y);
        As[r][cb + 2] = f2tf32(v0.z);
        As[r][cb + 3] = f2tf32(v0.w);
        As[r][cb + 4] = f2tf32(v1.x);
        As[r][cb + 5] = f2tf32(v1.y);
        As[r][cb + 6] = f2tf32(v1.z);
        As[r][cb + 7] = f2tf32(v1.w);
    }
    {   // B tile: 16 k x 128 cols
        #pragma unroll
        for (int it = 0; it < 2; it++) {
            int idx = tid + it * 256;        // 0..511 float4 units
            int rb = idx >> 5;               // 0..15
            int cb = (idx & 31) * 4;
            float4 bv = *(const float4*)(We + (size_t)rb * 128 + cb);
            Bs[rb][cb + 0] = f2tf32(bv.x);
            Bs[rb][cb + 1] = f2tf32(bv.y);
            Bs[rb][cb + 2] = f2tf32(bv.z);
            Bs[rb][cb + 3] = f2tf32(bv.w);
        }
    }
    __syncthreads();

    int lane = tid & 31, wid = tid >> 5;
    int g = lane >> 2, tg = lane & 3;
    float c[16][4];
    #pragma unroll
    for (int nt = 0; nt < 16; nt++)
        #pragma unroll
        for (int q = 0; q < 4; q++) c[nt][q] = 0.f;

    int r0 = wid * 16 + g;
    #pragma unroll
    for (int ks = 0; ks < 2; ks++) {
        int k8 = ks * 8;
        unsigned a0 = As[r0    ][k8 + tg];
        unsigned a1 = As[r0 + 8][k8 + tg];
        unsigned a2 = As[r0    ][k8 + tg + 4];
        unsigned a3 = As[r0 + 8][k8 + tg + 4];
        #pragma unroll
        for (int nt = 0; nt < 16; nt++) {
            unsigned b0 = Bs[k8 + tg    ][nt * 8 + g];
            unsigned b1 = Bs[k8 + tg + 4][nt * 8 + g];
            asm volatile(
                "mma.sync.aligned.m16n8k8.row.col.f32.tf32.tf32.f32 "
                "{%0,%1,%2,%3}, {%4,%5,%6,%7}, {%8,%9}, {%0,%1,%2,%3};"
                : "+f"(c[nt][0]), "+f"(c[nt][1]), "+f"(c[nt][2]), "+f"(c[nt][3])
                : "r"(a0), "r"(a1), "r"(a2), "r"(a3), "r"(b0), "r"(b1));
        }
    }

    int pos0 = base + wid * 16 + g;
    int pos1 = pos0 + 8;
    #pragma unroll
    for (int nt = 0; nt < 16; nt++) {
        int col = nt * 8 + 2 * tg;
        if (pos0 < EN)
            *(__half2*)(g_ee + (size_t)pos0 * 128 + col) = __floats2half2_rn(c[nt][0], c[nt][1]);
        if (pos1 < EN)
            *(__half2*)(g_ee + (size_t)pos1 * 128 + col) = __floats2half2_rn(c[nt][2], c[nt][3]);
    }
}

// ---------------- fused softmax aggregation (ee precomputed, streamed) ----------------
// One warp per destination node; ee read sequentially in CSR order.
__global__ void __launch_bounds__(256) k_fagg(
    const float* __restrict__ att, const float* __restrict__ cb, int E, int N)
{
    int tid = threadIdx.x;
    int lane = tid & 31;
    int c0 = lane * 4;
    int wrp = tid >> 5;
    int stride = gridDim.x * 8;
    float4 av  = *(const float4*)(att + c0);
    float4 cbv = *(const float4*)(cb + c0);

    for (int w = blockIdx.x * 8 + wrp; w < N; w += stride) {
        int beg = g_off[w], end = g_off[w + 1];
        float4 vxr = *(const float4*)(g_xr + (size_t)w * 128 + c0);

        float den = 0.f;
        float a0 = 0.f, a1 = 0.f, a2 = 0.f, a3 = 0.f;

        for (int j = beg; j < end; j++) {
            int src = g_es[j].y;
            float4 vxl = *(const float4*)(g_xl + (size_t)src * 128 + c0);
            uint2 eu = *(const uint2*)(g_ee + (size_t)j * 128 + c0);
            float2 f0 = __half22float2(*(const __half2*)&eu.x);
            float2 f1 = __half22float2(*(const __half2*)&eu.y);

            float m0 = vxl.x + vxr.x + f0.x;
            float m1 = vxl.y + vxr.y + f0.y;
            float m2 = vxl.z + vxr.z + f1.x;
            float m3 = vxl.w + vxr.w + f1.y;
            m0 = (m0 > 0.f) ? m0 : 0.2f * m0;
            m1 = (m1 > 0.f) ? m1 : 0.2f * m1;
            m2 = (m2 > 0.f) ? m2 : 0.2f * m2;
            m3 = (m3 > 0.f) ? m3 : 0.2f * m3;
            float p = m0 * av.x + m1 * av.y + m2 * av.z + m3 * av.w;
            // reduce within 8-lane head group (head = lane>>3)
            p += __shfl_xor_sync(0xffffffffu, p, 1);
            p += __shfl_xor_sync(0xffffffffu, p, 2);
            p += __shfl_xor_sync(0xffffffffu, p, 4);

            float wgt = __expf(p);   // logits are small; no max-shift needed
            den += wgt;
            a0 += wgt * vxl.x;
            a1 += wgt * vxl.y;
            a2 += wgt * vxl.z;
            a3 += wgt * vxl.w;
        }

        float inv = 1.f / den;
        float o0 = a0 * inv + cbv.x;
        float o1 = a1 * inv + cbv.y;
        float o2 = a2 * inv + cbv.z;
        float o3 = a3 * inv + cbv.w;
        o0 = (o0 > 0.f) ? o0 : expm1f(o0);
        o1 = (o1 > 0.f) ? o1 : expm1f(o1);
        o2 = (o2 > 0.f) ? o2 : expm1f(o2);
        o3 = (o3 > 0.f) ? o3 : expm1f(o3);
        *(float4*)(g_h + (size_t)w * 128 + c0) = make_float4(o0, o1, o2, o3);
    }
}

// ---------------- LayerNorm + MLP head (one warp per node, grid-stride) ----------------
__global__ void __launch_bounds__(256) k_head(
    const float* __restrict__ ln_g, const float* __restrict__ ln_b,
    const float* __restrict__ h1w, const float* __restrict__ h1b,
    const float* __restrict__ h2w, const float* __restrict__ h2b,
    float* __restrict__ out, int N)
{
    __shared__ __align__(16) float sW1[128 * 64];
    __shared__ float sg[128], sb[128], sb1[64], sW2[64 * 3], sb2[4];
    __shared__ __align__(16) float srow[8][128];
    int tid = threadIdx.x;
    for (int i = tid; i < 128 * 64; i += blockDim.x) sW1[i] = h1w[i];
    if (tid < 128) { sg[tid] = ln_g[tid]; sb[tid] = ln_b[tid]; }
    if (tid < 64)  sb1[tid] = h1b[tid];
    if (tid < 192) sW2[tid] = h2w[tid];
    if (tid < 3)   sb2[tid] = h2b[tid];
    __syncthreads();

    int wrp = tid >> 5;
    int lane = tid & 31;
    int c0 = lane * 4;
    int stride = gridDim.x * 8;

    for (int w = blockIdx.x * 8 + wrp; w < N; w += stride) {
        float4 hv = *(const float4*)(g_h + (size_t)w * 128 + c0);
        float sum = hv.x + hv.y + hv.z + hv.w;
        #pragma unroll
        for (int o = 16; o >= 1; o >>= 1) sum += __shfl_xor_sync(0xffffffffu, sum, o);
        float mu = sum * (1.f / 128.f);
        float dx = hv.x - mu, dy = hv.y - mu, dz = hv.z - mu, dw = hv.w - mu;
        float sq = dx * dx + dy * dy + dz * dz + dw * dw;
        #pragma unroll
        for (int o = 16; o >= 1; o >>= 1) sq += __shfl_xor_sync(0xffffffffu, sq, o);
        float rstd = rsqrtf(sq * (1.f / 128.f) + 1e-5f);
        srow[wrp][c0 + 0] = dx * rstd * sg[c0 + 0] + sb[c0 + 0];
        srow[wrp][c0 + 1] = dy * rstd * sg[c0 + 1] + sb[c0 + 1];
        srow[wrp][c0 + 2] = dz * rstd * sg[c0 + 2] + sb[c0 + 2];
        srow[wrp][c0 + 3] = dw * rstd * sg[c0 + 3] + sb[c0 + 3];
        __syncwarp();

        const float2* W1v = (const float2*)sW1;
        float a0 = sb1[2 * lane], a1 = sb1[2 * lane + 1];
        #pragma unroll 8
        for (int k = 0; k < 128; k++) {
            float r = srow[wrp][k];
            float2 wvv = W1v[k * 32 + lane];
            a0 += r * wvv.x;
            a1 += r * wvv.y;
        }
        a0 = fmaxf(a0, 0.f);
        a1 = fmaxf(a1, 0.f);
        float p0 = a0 * sW2[(2 * lane) * 3 + 0] + a1 * sW2[(2 * lane + 1) * 3 + 0];
        float p1 = a0 * sW2[(2 * lane) * 3 + 1] + a1 * sW2[(2 * lane + 1) * 3 + 1];
        float p2 = a0 * sW2[(2 * lane) * 3 + 2] + a1 * sW2[(2 * lane + 1) * 3 + 2];
        #pragma unroll
        for (int o = 16; o >= 1; o >>= 1) {
            p0 += __shfl_xor_sync(0xffffffffu, p0, o);
            p1 += __shfl_xor_sync(0xffffffffu, p1, o);
            p2 += __shfl_xor_sync(0xffffffffu, p2, o);
        }
        if (lane == 0) {
            out[(size_t)w * 3 + 0] = p0 + sb2[0];
            out[(size_t)w * 3 + 1] = p1 + sb2[1];
            out[(size_t)w * 3 + 2] = p2 + sb2[2];
        }
        __syncwarp();
    }
}

// ---------------- launch ----------------
extern "C" void kernel_launch(void* const* d_in, const int* in_sizes, int n_in,
                              void* d_out, int out_size)
{
    const float* x    = (const float*)d_in[0];
    const void*  ei   = d_in[1];
    const float* ea   = (const float*)d_in[2];
    const float* in_w = (const float*)d_in[3];
    const float* in_b = (const float*)d_in[4];
    const float* Wl   = (const float*)d_in[5];
    const float* bl   = (const float*)d_in[6];
    const float* Wr   = (const float*)d_in[7];
    const float* br   = (const float*)d_in[8];
    const float* We   = (const float*)d_in[9];
    const float* att  = (const float*)d_in[10];
    const float* cb   = (const float*)d_in[11];
    const float* ln_g = (const float*)d_in[12];
    const float* ln_b = (const float*)d_in[13];
    const float* h1w  = (const float*)d_in[14];
    const float* h1b  = (const float*)d_in[15];
    const float* h2w  = (const float*)d_in[16];
    const float* h2b  = (const float*)d_in[17];
    float* out = (float*)d_out;

    int N = in_sizes[0] / 128;
    int E = in_sizes[2] / 16;
    int EN = E + N;
    int nb1024 = (N + 1023) / 1024;
    int geb = (EN + 127) / 128;

    k_detect<<<1, 256>>>((const int*)ei);
    k_zero<<<(N + 255) / 256, 256>>>(N);
    k_hist<<<(E + 255) / 256, 256>>>(ei, E);
    k_scan1<<<nb1024, 1024>>>(N);
    k_scan2<<<1, 128>>>(nb1024);
    k_scan3<<<(N + 1023) / 1024, 1024>>>(N);
    k_fill<<<(EN + 255) / 256, 256>>>(ei, E, EN);
    k_loopattr<<<(N + 7) / 8, 256>>>(ea, E, N);
    k_combine<<<dim3(128, 2), 128>>>(in_w, in_b, Wl, bl, Wr, br);

    int gb = (N + 127) / 128;
    // layer 0: xl = x @ (in_w@Wl0), xr = x @ (in_w@Wr0)  (composed weights)
    mma_gemm<<<dim3(gb, 2), 256>>>(x,
                                   nullptr, nullptr, /*bsel=*/0, /*dst=*/1,
                                   nullptr, nullptr, /*bsel=*/1, /*dst=*/2, N);
    k_eegemm<<<geb, 256>>>(ea, We, E, EN);
    k_fagg<<<(N + 7) / 8, 256>>>(att, cb, E, N);

    // layer 1: from g_h
    mma_gemm<<<dim3(gb, 2), 256>>>(nullptr,
                                   Wl + (size_t)128 * 128, bl + 128, -1, /*dst=*/1,
                                   Wr + (size_t)128 * 128, br + 128, -1, /*dst=*/2, N);
    k_eegemm<<<geb, 256>>>(ea, We + (size_t)16 * 128, E, EN);
    k_fagg<<<(N + 7) / 8, 256>>>(att + 128, cb + 128, E, N);

    k_head<<<592, 256>>>(ln_g, ln_b, h1w, h1b, h2w, h2b, out, N);
}

// round 14
// speedup vs baseline: 1.5392x; 1.5392x over previous
#include <cuda_runtime.h>
#include <cuda_fp16.h>
#include <math.h>

// Problem constants (fixed by the dataset)
#define NN   50000
#define EEDG 600000
#define DD   128
#define EDIM 16
#define ENMAX (EEDG + NN)

// ---------------- device scratch (no allocations allowed) ----------------
__device__ int   g_is64;
__device__ int   g_cnt[NN];
__device__ int   g_off[NN + 1];
__device__ int   g_cur[NN];
__device__ int   g_part[128];
__device__ int2  g_es[ENMAX];          // (eid, src) in CSR-by-dst order
__device__ float g_loop[NN * EDIM];
__device__ float g_h[(size_t)NN * DD];
__device__ float g_xl[(size_t)NN * DD];
__device__ float g_xr[(size_t)NN * DD];
__device__ float g_wc[2 * DD * DD];    // composed layer-0 weights
__device__ float g_bc[2 * DD];         // composed layer-0 biases

// edge_index may arrive as int32 (jax x64 disabled) or int64. Detect on device.
__device__ __forceinline__ int eidx(const void* ei, long long i) {
    if (g_is64) return (int)((const long long*)ei)[i];
    return ((const int*)ei)[i];
}

__global__ void k_detect(const int* ei32) {
    __shared__ int s_any;
    if (threadIdx.x == 0) s_any = 0;
    __syncthreads();
    int v = ei32[2 * threadIdx.x + 1];
    if (v != 0) atomicOr(&s_any, 1);
    __syncthreads();
    if (threadIdx.x == 0) g_is64 = (s_any == 0);
}

__global__ void k_zero(int n) {
    int i = blockIdx.x * blockDim.x + threadIdx.x;
    if (i < n) g_cnt[i] = 0;
}

__global__ void k_hist(const void* ei, int E) {
    int e = blockIdx.x * blockDim.x + threadIdx.x;
    if (e < E) {
        int d = eidx(ei, (long long)E + e);
        atomicAdd(&g_cnt[d], 1);
    }
}

// ---- 3-phase scan of (cnt[i]+1) -> g_off (exclusive offsets), g_cur ----
__global__ void k_scan1(int n) {
    __shared__ int wsum[32];
    int tid = threadIdx.x, lane = tid & 31, wid = tid >> 5;
    int i = blockIdx.x * 1024 + tid;
    int v = (i < n) ? (g_cnt[i] + 1) : 0;
    int s = v;
    #pragma unroll
    for (int o = 1; o < 32; o <<= 1) {
        int t = __shfl_up_sync(0xffffffffu, s, o);
        if (lane >= o) s += t;
    }
    if (lane == 31) wsum[wid] = s;
    __syncthreads();
    if (wid == 0) {
        int ws = wsum[lane];
        #pragma unroll
        for (int o = 1; o < 32; o <<= 1) {
            int t = __shfl_up_sync(0xffffffffu, ws, o);
            if (lane >= o) ws += t;
        }
        wsum[lane] = ws;
    }
    __syncthreads();
    int incl = s + (wid ? wsum[wid - 1] : 0);
    if (i < n) g_off[i + 1] = incl;
    if (tid == 1023) g_part[blockIdx.x] = incl;
}

__global__ void k_scan2(int nb) {
    __shared__ int s[128];
    int t = threadIdx.x;
    int v = (t < nb) ? g_part[t] : 0;
    s[t] = v;
    __syncthreads();
    for (int o = 1; o < 128; o <<= 1) {
        int x = (t >= o) ? s[t - o] : 0;
        __syncthreads();
        s[t] += x;
        __syncthreads();
    }
    if (t < nb) g_part[t] = s[t];
}

__global__ void k_scan3(int n) {
    int i = blockIdx.x * blockDim.x + threadIdx.x;
    if (i == 0) g_off[0] = 0;
    if (i < n) {
        int b = i >> 10;
        int carry = (b > 0) ? g_part[b - 1] : 0;
        int off = g_off[i + 1] + carry;
        g_off[i + 1] = off;
        g_cur[i] = off - (g_cnt[i] + 1);
    }
}

__global__ void k_fill(const void* ei, int E, int EN) {
    int e = blockIdx.x * blockDim.x + threadIdx.x;
    if (e < EN) {
        int d, s;
        if (e < E) {
            d = eidx(ei, (long long)E + e);
            s = eidx(ei, e);
        } else {
            d = e - E;
            s = e - E;
        }
        int p = atomicAdd(&g_cur[d], 1);
        g_es[p] = make_int2(e, s);
    }
}

// loop_attr[i] = mean of incoming (real) edge_attr
__global__ void k_loopattr(const float* __restrict__ ea, int E, int N) {
    int w = blockIdx.x * (blockDim.x >> 5) + (threadIdx.x >> 5);
    int lane = threadIdx.x & 31;
    if (w >= N) return;
    int beg = g_off[w], end = g_off[w + 1];
    if (lane < 16) {
        float s = 0.f;
        for (int j = beg; j < end; j++) {
            int eid = g_es[j].x;
            if (eid < E) s += ea[(size_t)eid * 16 + lane];
        }
        float deg = (float)(end - beg - 1);
        g_loop[w * 16 + lane] = s / fmaxf(deg, 1.0f);
    }
}

// ---- compose layer-0 weights: g_wc[y] = in_w @ W, g_bc[y] = in_b @ W + b ----
__global__ void k_combine(const float* __restrict__ in_w, const float* __restrict__ in_b,
                          const float* __restrict__ Wl, const float* __restrict__ bl,
                          const float* __restrict__ Wr, const float* __restrict__ br)
{
    const float* W = blockIdx.y ? Wr : Wl;
    const float* bb = blockIdx.y ? br : bl;
    __shared__ float srow[128];
    int col = threadIdx.x;
    int row = blockIdx.x;
    srow[col] = in_w[row * 128 + col];
    __syncthreads();
    float s = 0.f;
    for (int k = 0; k < 128; k++) s += srow[k] * W[k * 128 + col];
    g_wc[blockIdx.y * 128 * 128 + row * 128 + col] = s;
    if (row == 0) {
        float t = bb[col];
        for (int k = 0; k < 128; k++) t += in_b[k] * W[k * 128 + col];
        g_bc[blockIdx.y * 128 + col] = t;
    }
}

// ---------------- tf32 tensor-core GEMM ----------------
__device__ __forceinline__ unsigned f2tf32(float f) {
    unsigned r;
    asm("cvt.rna.tf32.f32 %0, %1;" : "=r"(r) : "f"(f));
    return r;
}

__global__ void __launch_bounds__(256) mma_gemm(
    const float* __restrict__ A_in,
    const float* __restrict__ B0, const float* __restrict__ bias0, int bsel0, int dst0,
    const float* __restrict__ B1, const float* __restrict__ bias1, int bsel1, int dst1,
    int M)
{
    const float* A = (A_in != nullptr) ? A_in : (const float*)g_h;
    const float* B;
    const float* bias;
    int dst;
    if (blockIdx.y) {
        B = (bsel1 >= 0) ? (const float*)(g_wc + bsel1 * 128 * 128) : B1;
        bias = (bsel1 >= 0) ? (const float*)(g_bc + bsel1 * 128) : bias1;
        dst = dst1;
    } else {
        B = (bsel0 >= 0) ? (const float*)(g_wc + bsel0 * 128 * 128) : B0;
        bias = (bsel0 >= 0) ? (const float*)(g_bc + bsel0 * 128) : bias0;
        dst = dst0;
    }
    float* C = (dst == 0) ? g_h : (dst == 1) ? g_xl : g_xr;

    __shared__ unsigned As[128][36];
    __shared__ unsigned Bs[32][136];

    const int tid = threadIdx.x;
    const int lane = tid & 31;
    const int wid = tid >> 5;
    const int wm = wid >> 1;
    const int wn = wid & 1;
    const int g  = lane >> 2;
    const int tg = lane & 3;
    const int rowBase = blockIdx.x * 128;

    float c[2][8][4];
    #pragma unroll
    for (int mt = 0; mt < 2; mt++)
        #pragma unroll
        for (int nt = 0; nt < 8; nt++)
            #pragma unroll
            for (int q = 0; q < 4; q++) c[mt][nt][q] = 0.f;

    for (int k0 = 0; k0 < 128; k0 += 32) {
        #pragma unroll
        for (int it = 0; it < 4; it++) {
            int linear = tid + it * 256;
            int r  = linear >> 3;
            int c4 = (linear & 7) * 4;
            float4 v = make_float4(0.f, 0.f, 0.f, 0.f);
            int row = rowBase + r;
            if (row < M) v = *(const float4*)(A + (size_t)row * 128 + k0 + c4);
            As[r][c4 + 0] = f2tf32(v.x);
            As[r][c4 + 1] = f2tf32(v.y);
            As[r][c4 + 2] = f2tf32(v.z);
            As[r][c4 + 3] = f2tf32(v.w);

            int rb  = linear >> 5;
            int cb4 = (linear & 31) * 4;
            float4 bv = *(const float4*)(B + (size_t)(k0 + rb) * 128 + cb4);
            Bs[rb][cb4 + 0] = f2tf32(bv.x);
            Bs[rb][cb4 + 1] = f2tf32(bv.y);
            Bs[rb][cb4 + 2] = f2tf32(bv.z);
            Bs[rb][cb4 + 3] = f2tf32(bv.w);
        }
        __syncthreads();

        #pragma unroll
        for (int ks = 0; ks < 4; ks++) {
            int k8 = ks * 8;
            unsigned a[2][4];
            #pragma unroll
            for (int mt = 0; mt < 2; mt++) {
                int r0 = wm * 32 + mt * 16 + g;
                a[mt][0] = As[r0    ][k8 + tg];
                a[mt][1] = As[r0 + 8][k8 + tg];
                a[mt][2] = As[r0    ][k8 + tg + 4];
                a[mt][3] = As[r0 + 8][k8 + tg + 4];
            }
            unsigned b[8][2];
            #pragma unroll
            for (int nt = 0; nt < 8; nt++) {
                int col = wn * 64 + nt * 8 + g;
                b[nt][0] = Bs[k8 + tg    ][col];
                b[nt][1] = Bs[k8 + tg + 4][col];
            }
            #pragma unroll
            for (int mt = 0; mt < 2; mt++)
                #pragma unroll
                for (int nt = 0; nt < 8; nt++) {
                    asm volatile(
                        "mma.sync.aligned.m16n8k8.row.col.f32.tf32.tf32.f32 "
                        "{%0,%1,%2,%3}, {%4,%5,%6,%7}, {%8,%9}, {%0,%1,%2,%3};"
                        : "+f"(c[mt][nt][0]), "+f"(c[mt][nt][1]),
                          "+f"(c[mt][nt][2]), "+f"(c[mt][nt][3])
                        : "r"(a[mt][0]), "r"(a[mt][1]), "r"(a[mt][2]), "r"(a[mt][3]),
                          "r"(b[nt][0]), "r"(b[nt][1]));
                }
        }
        __syncthreads();
    }

    #pragma unroll
    for (int mt = 0; mt < 2; mt++) {
        int row0 = rowBase + wm * 32 + mt * 16 + g;
        #pragma unroll
        for (int nt = 0; nt < 8; nt++) {
            int col = wn * 64 + nt * 8 + 2 * tg;
            float b0 = bias[col], b1 = bias[col + 1];
            if (row0 < M) {
                float2 o = make_float2(c[mt][nt][0] + b0, c[mt][nt][1] + b1);
                *(float2*)(C + (size_t)row0 * 128 + col) = o;
            }
            int row1 = row0 + 8;
            if (row1 < M) {
                float2 o = make_float2(c[mt][nt][2] + b0, c[mt][nt][3] + b1);
                *(float2*)(C + (size_t)row1 * 128 + col) = o;
            }
        }
    }
}

// ---------------- fused edge-logit + softmax aggregation ----------------
// One warp per destination node; single pass over incoming CSR edges.
// We held in smem as fp16: one LDS.64 per k per lane (half crossbar traffic),
// HFMA2 dot-product. Logits are small -> plain exp (softmax-invariant).
__global__ void __launch_bounds__(256) k_fagg(
    const float* __restrict__ ea,
    const float* __restrict__ We, const float* __restrict__ att,
    const float* __restrict__ cb, int E, int N)
{
    __shared__ __align__(16) __half sWe[16 * 128];
    __shared__ __align__(16) float sAtt[128];
    __shared__ float sCb[128];
    int tid = threadIdx.x;
    for (int i = tid; i < 16 * 128; i += blockDim.x) sWe[i] = __float2half(We[i]);
    if (tid < 128) { sAtt[tid] = att[tid]; sCb[tid] = cb[tid]; }
    __syncthreads();

    int lane = tid & 31;
    int c0 = lane * 4;
    int wrp = tid >> 5;
    int stride = gridDim.x * 8;
    float4 av = *(const float4*)(sAtt + c0);

    for (int w = blockIdx.x * 8 + wrp; w < N; w += stride) {
        int beg = g_off[w], end = g_off[w + 1];
        float4 vxr = *(const float4*)(g_xr + (size_t)w * 128 + c0);

        float den = 0.f;
        float a0 = 0.f, a1 = 0.f, a2 = 0.f, a3 = 0.f;

        for (int j = beg; j < end; j++) {
            int2 es = g_es[j];
            const float* eav = (es.x < E) ? (ea + (size_t)es.x * 16)
                                          : (g_loop + (size_t)(es.x - E) * 16);
            float myea = (lane < 16) ? eav[lane] : 0.f;
            float4 vxl = *(const float4*)(g_xl + (size_t)es.y * 128 + c0);

            __half2 acc01 = __float2half2_rn(0.f);
            __half2 acc23 = __float2half2_rn(0.f);
            #pragma unroll
            for (int k = 0; k < 16; k++) {
                float aa = __shfl_sync(0xffffffffu, myea, k);
                __half2 aah = __float2half2_rn(aa);
                uint2 wk = *(const uint2*)(sWe + k * 128 + c0);   // 8B: channels c0..c0+3
                acc01 = __hfma2(aah, *(__half2*)&wk.x, acc01);
                acc23 = __hfma2(aah, *(__half2*)&wk.y, acc23);
            }
            float2 e01 = __half22float2(acc01);
            float2 e23 = __half22float2(acc23);

            float m0 = vxl.x + vxr.x + e01.x;
            float m1 = vxl.y + vxr.y + e01.y;
            float m2 = vxl.z + vxr.z + e23.x;
            float m3 = vxl.w + vxr.w + e23.y;
            m0 = (m0 > 0.f) ? m0 : 0.2f * m0;
            m1 = (m1 > 0.f) ? m1 : 0.2f * m1;
            m2 = (m2 > 0.f) ? m2 : 0.2f * m2;
            m3 = (m3 > 0.f) ? m3 : 0.2f * m3;
            float p = m0 * av.x + m1 * av.y + m2 * av.z + m3 * av.w;
            // reduce within 8-lane head group (head = lane>>3)
            p += __shfl_xor_sync(0xffffffffu, p, 1);
            p += __shfl_xor_sync(0xffffffffu, p, 2);
            p += __shfl_xor_sync(0xffffffffu, p, 4);

            float wgt = __expf(p);
            den += wgt;
            a0 += wgt * vxl.x;
            a1 += wgt * vxl.y;
            a2 += wgt * vxl.z;
            a3 += wgt * vxl.w;
        }

        float inv = 1.f / den;
        float o0 = a0 * inv + sCb[c0 + 0];
        float o1 = a1 * inv + sCb[c0 + 1];
        float o2 = a2 * inv + sCb[c0 + 2];
        float o3 = a3 * inv + sCb[c0 + 3];
        o0 = (o0 > 0.f) ? o0 : expm1f(o0);
        o1 = (o1 > 0.f) ? o1 : expm1f(o1);
        o2 = (o2 > 0.f) ? o2 : expm1f(o2);
        o3 = (o3 > 0.f) ? o3 : expm1f(o3);
        *(float4*)(g_h + (size_t)w * 128 + c0) = make_float4(o0, o1, o2, o3);
    }
}

// ---------------- LayerNorm + MLP head (one warp per node, grid-stride) ----------------
__global__ void __launch_bounds__(256) k_head(
    const float* __restrict__ ln_g, const float* __restrict__ ln_b,
    const float* __restrict__ h1w, const float* __restrict__ h1b,
    const float* __restrict__ h2w, const float* __restrict__ h2b,
    float* __restrict__ out, int N)
{
    __shared__ __align__(16) float sW1[128 * 64];
    __shared__ float sg[128], sb[128], sb1[64], sW2[64 * 3], sb2[4];
    __shared__ __align__(16) float srow[8][128];
    int tid = threadIdx.x;
    for (int i = tid; i < 128 * 64; i += blockDim.x) sW1[i] = h1w[i];
    if (tid < 128) { sg[tid] = ln_g[tid]; sb[tid] = ln_b[tid]; }
    if (tid < 64)  sb1[tid] = h1b[tid];
    if (tid < 192) sW2[tid] = h2w[tid];
    if (tid < 3)   sb2[tid] = h2b[tid];
    __syncthreads();

    int wrp = tid >> 5;
    int lane = tid & 31;
    int c0 = lane * 4;
    int stride = gridDim.x * 8;

    for (int w = blockIdx.x * 8 + wrp; w < N; w += stride) {
        float4 hv = *(const float4*)(g_h + (size_t)w * 128 + c0);
        float sum = hv.x + hv.y + hv.z + hv.w;
        #pragma unroll
        for (int o = 16; o >= 1; o >>= 1) sum += __shfl_xor_sync(0xffffffffu, sum, o);
        float mu = sum * (1.f / 128.f);
        float dx = hv.x - mu, dy = hv.y - mu, dz = hv.z - mu, dw = hv.w - mu;
        float sq = dx * dx + dy * dy + dz * dz + dw * dw;
        #pragma unroll
        for (int o = 16; o >= 1; o >>= 1) sq += __shfl_xor_sync(0xffffffffu, sq, o);
        float rstd = rsqrtf(sq * (1.f / 128.f) + 1e-5f);
        srow[wrp][c0 + 0] = dx * rstd * sg[c0 + 0] + sb[c0 + 0];
        srow[wrp][c0 + 1] = dy * rstd * sg[c0 + 1] + sb[c0 + 1];
        srow[wrp][c0 + 2] = dz * rstd * sg[c0 + 2] + sb[c0 + 2];
        srow[wrp][c0 + 3] = dw * rstd * sg[c0 + 3] + sb[c0 + 3];
        __syncwarp();

        const float2* W1v = (const float2*)sW1;
        float a0 = sb1[2 * lane], a1 = sb1[2 * lane + 1];
        #pragma unroll 8
        for (int k = 0; k < 128; k++) {
            float r = srow[wrp][k];
            float2 wvv = W1v[k * 32 + lane];
            a0 += r * wvv.x;
            a1 += r * wvv.y;
        }
        a0 = fmaxf(a0, 0.f);
        a1 = fmaxf(a1, 0.f);
        float p0 = a0 * sW2[(2 * lane) * 3 + 0] + a1 * sW2[(2 * lane + 1) * 3 + 0];
        float p1 = a0 * sW2[(2 * lane) * 3 + 1] + a1 * sW2[(2 * lane + 1) * 3 + 1];
        float p2 = a0 * sW2[(2 * lane) * 3 + 2] + a1 * sW2[(2 * lane + 1) * 3 + 2];
        #pragma unroll
        for (int o = 16; o >= 1; o >>= 1) {
            p0 += __shfl_xor_sync(0xffffffffu, p0, o);
            p1 += __shfl_xor_sync(0xffffffffu, p1, o);
            p2 += __shfl_xor_sync(0xffffffffu, p2, o);
        }
        if (lane == 0) {
            out[(size_t)w * 3 + 0] = p0 + sb2[0];
            out[(size_t)w * 3 + 1] = p1 + sb2[1];
            out[(size_t)w * 3 + 2] = p2 + sb2[2];
        }
        __syncwarp();
    }
}

// ---------------- launch ----------------
extern "C" void kernel_launch(void* const* d_in, const int* in_sizes, int n_in,
                              void* d_out, int out_size)
{
    const float* x    = (const float*)d_in[0];
    const void*  ei   = d_in[1];
    const float* ea   = (const float*)d_in[2];
    const float* in_w = (const float*)d_in[3];
    const float* in_b = (const float*)d_in[4];
    const float* Wl   = (const float*)d_in[5];
    const float* bl   = (const float*)d_in[6];
    const float* Wr   = (const float*)d_in[7];
    const float* br   = (const float*)d_in[8];
    const float* We   = (const float*)d_in[9];
    const float* att  = (const float*)d_in[10];
    const float* cb   = (const float*)d_in[11];
    const float* ln_g = (const float*)d_in[12];
    const float* ln_b = (const float*)d_in[13];
    const float* h1w  = (const float*)d_in[14];
    const float* h1b  = (const float*)d_in[15];
    const float* h2w  = (const float*)d_in[16];
    const float* h2b  = (const float*)d_in[17];
    float* out = (float*)d_out;

    int N = in_sizes[0] / 128;
    int E = in_sizes[2] / 16;
    int EN = E + N;
    int nb1024 = (N + 1023) / 1024;

    k_detect<<<1, 256>>>((const int*)ei);
    k_zero<<<(N + 255) / 256, 256>>>(N);
    k_hist<<<(E + 255) / 256, 256>>>(ei, E);
    k_scan1<<<nb1024, 1024>>>(N);
    k_scan2<<<1, 128>>>(nb1024);
    k_scan3<<<(N + 1023) / 1024, 1024>>>(N);
    k_fill<<<(EN + 255) / 256, 256>>>(ei, E, EN);
    k_loopattr<<<(N + 7) / 8, 256>>>(ea, E, N);
    k_combine<<<dim3(128, 2), 128>>>(in_w, in_b, Wl, bl, Wr, br);

    int gb = (N + 127) / 128;
    // layer 0: xl = x @ (in_w@Wl0), xr = x @ (in_w@Wr0)  (composed weights)
    mma_gemm<<<dim3(gb, 2), 256>>>(x,
                                   nullptr, nullptr, /*bsel=*/0, /*dst=*/1,
                                   nullptr, nullptr, /*bsel=*/1, /*dst=*/2, N);
    k_fagg<<<(N + 7) / 8, 256>>>(ea, We, att, cb, E, N);

    // layer 1: from g_h
    mma_gemm<<<dim3(gb, 2), 256>>>(nullptr,
                                   Wl + (size_t)128 * 128, bl + 128, -1, /*dst=*/1,
                                   Wr + (size_t)128 * 128, br + 128, -1, /*dst=*/2, N);
    k_fagg<<<(N + 7) / 8, 256>>>(ea, We + (size_t)16 * 128, att + 128, cb + 128, E, N);

    k_head<<<592, 256>>>(ln_g, ln_b, h1w, h1b, h2w, h2b, out, N);
}

// round 16
// speedup vs baseline: 1.7977x; 1.1680x over previous
#include <cuda_runtime.h>
#include <cuda_fp16.h>
#include <math.h>

// Problem constants (fixed by the dataset)
#define NN   50000
#define EEDG 600000
#define DD   128
#define EDIM 16
#define ENMAX (EEDG + NN)

// ---------------- device scratch (no allocations allowed) ----------------
__device__ int   g_is64;
__device__ int   g_cnt[NN];
__device__ int   g_off[NN + 1];
__device__ int   g_cur[NN];
__device__ int   g_part[128];
__device__ int2  g_es[ENMAX];          // (eid, src) in CSR-by-dst order
__device__ float g_loop[NN * EDIM];
__device__ float g_h[(size_t)NN * DD];
__device__ float g_xl[(size_t)NN * DD];
__device__ float g_xr[(size_t)NN * DD];
__device__ float g_wc[2 * DD * DD];    // composed layer-0 weights
__device__ float g_bc[2 * DD];         // composed layer-0 biases

// edge_index may arrive as int32 (jax x64 disabled) or int64. Detect on device.
__device__ __forceinline__ int eidx(const void* ei, long long i) {
    if (g_is64) return (int)((const long long*)ei)[i];
    return ((const int*)ei)[i];
}

__global__ void k_detect(const int* ei32) {
    __shared__ int s_any;
    if (threadIdx.x == 0) s_any = 0;
    __syncthreads();
    int v = ei32[2 * threadIdx.x + 1];
    if (v != 0) atomicOr(&s_any, 1);
    __syncthreads();
    if (threadIdx.x == 0) g_is64 = (s_any == 0);
}

__global__ void k_zero(int n) {
    int i = blockIdx.x * blockDim.x + threadIdx.x;
    if (i < n) g_cnt[i] = 0;
}

__global__ void k_hist(const void* ei, int E) {
    int e = blockIdx.x * blockDim.x + threadIdx.x;
    if (e < E) {
        int d = eidx(ei, (long long)E + e);
        atomicAdd(&g_cnt[d], 1);
    }
}

// ---- 3-phase scan of (cnt[i]+1) -> g_off (exclusive offsets), g_cur ----
__global__ void k_scan1(int n) {
    __shared__ int wsum[32];
    int tid = threadIdx.x, lane = tid & 31, wid = tid >> 5;
    int i = blockIdx.x * 1024 + tid;
    int v = (i < n) ? (g_cnt[i] + 1) : 0;
    int s = v;
    #pragma unroll
    for (int o = 1; o < 32; o <<= 1) {
        int t = __shfl_up_sync(0xffffffffu, s, o);
        if (lane >= o) s += t;
    }
    if (lane == 31) wsum[wid] = s;
    __syncthreads();
    if (wid == 0) {
        int ws = wsum[lane];
        #pragma unroll
        for (int o = 1; o < 32; o <<= 1) {
            int t = __shfl_up_sync(0xffffffffu, ws, o);
            if (lane >= o) ws += t;
        }
        wsum[lane] = ws;
    }
    __syncthreads();
    int incl = s + (wid ? wsum[wid - 1] : 0);
    if (i < n) g_off[i + 1] = incl;
    if (tid == 1023) g_part[blockIdx.x] = incl;
}

__global__ void k_scan2(int nb) {
    __shared__ int s[128];
    int t = threadIdx.x;
    int v = (t < nb) ? g_part[t] : 0;
    s[t] = v;
    __syncthreads();
    for (int o = 1; o < 128; o <<= 1) {
        int x = (t >= o) ? s[t - o] : 0;
        __syncthreads();
        s[t] += x;
        __syncthreads();
    }
    if (t < nb) g_part[t] = s[t];
}

__global__ void k_scan3(int n) {
    int i = blockIdx.x * blockDim.x + threadIdx.x;
    if (i == 0) g_off[0] = 0;
    if (i < n) {
        int b = i >> 10;
        int carry = (b > 0) ? g_part[b - 1] : 0;
        int off = g_off[i + 1] + carry;
        g_off[i + 1] = off;
        g_cur[i] = off - (g_cnt[i] + 1);
    }
}

__global__ void k_fill(const void* ei, int E, int EN) {
    int e = blockIdx.x * blockDim.x + threadIdx.x;
    if (e < EN) {
        int d, s;
        if (e < E) {
            d = eidx(ei, (long long)E + e);
            s = eidx(ei, e);
        } else {
            d = e - E;
            s = e - E;
        }
        int p = atomicAdd(&g_cur[d], 1);
        g_es[p] = make_int2(e, s);
    }
}

// loop_attr[i] = mean of incoming (real) edge_attr
__global__ void k_loopattr(const float* __restrict__ ea, int E, int N) {
    int w = blockIdx.x * (blockDim.x >> 5) + (threadIdx.x >> 5);
    int lane = threadIdx.x & 31;
    if (w >= N) return;
    int beg = g_off[w], end = g_off[w + 1];
    if (lane < 16) {
        float s = 0.f;
        for (int j = beg; j < end; j++) {
            int eid = g_es[j].x;
            if (eid < E) s += ea[(size_t)eid * 16 + lane];
        }
        float deg = (float)(end - beg - 1);
        g_loop[w * 16 + lane] = s / fmaxf(deg, 1.0f);
    }
}

// ---- compose layer-0 weights: g_wc[y] = in_w @ W, g_bc[y] = in_b @ W + b ----
__global__ void k_combine(const float* __restrict__ in_w, const float* __restrict__ in_b,
                          const float* __restrict__ Wl, const float* __restrict__ bl,
                          const float* __restrict__ Wr, const float* __restrict__ br)
{
    const float* W = blockIdx.y ? Wr : Wl;
    const float* bb = blockIdx.y ? br : bl;
    __shared__ float srow[128];
    int col = threadIdx.x;
    int row = blockIdx.x;
    srow[col] = in_w[row * 128 + col];
    __syncthreads();
    float s = 0.f;
    for (int k = 0; k < 128; k++) s += srow[k] * W[k * 128 + col];
    g_wc[blockIdx.y * 128 * 128 + row * 128 + col] = s;
    if (row == 0) {
        float t = bb[col];
        for (int k = 0; k < 128; k++) t += in_b[k] * W[k * 128 + col];
        g_bc[blockIdx.y * 128 + col] = t;
    }
}

// ---------------- tf32 tensor-core GEMM ----------------
__device__ __forceinline__ unsigned f2tf32(float f) {
    unsigned r;
    asm("cvt.rna.tf32.f32 %0, %1;" : "=r"(r) : "f"(f));
    return r;
}

__global__ void __launch_bounds__(256) mma_gemm(
    const float* __restrict__ A_in,
    const float* __restrict__ B0, const float* __restrict__ bias0, int bsel0, int dst0,
    const float* __restrict__ B1, const float* __restrict__ bias1, int bsel1, int dst1,
    int M)
{
    const float* A = (A_in != nullptr) ? A_in : (const float*)g_h;
    const float* B;
    const float* bias;
    int dst;
    if (blockIdx.y) {
        B = (bsel1 >= 0) ? (const float*)(g_wc + bsel1 * 128 * 128) : B1;
        bias = (bsel1 >= 0) ? (const float*)(g_bc + bsel1 * 128) : bias1;
        dst = dst1;
    } else {
        B = (bsel0 >= 0) ? (const float*)(g_wc + bsel0 * 128 * 128) : B0;
        bias = (bsel0 >= 0) ? (const float*)(g_bc + bsel0 * 128) : bias0;
        dst = dst0;
    }
    float* C = (dst == 0) ? g_h : (dst == 1) ? g_xl : g_xr;

    __shared__ unsigned As[128][36];
    __shared__ unsigned Bs[32][136];

    const int tid = threadIdx.x;
    const int lane = tid & 31;
    const int wid = tid >> 5;
    const int wm = wid >> 1;
    const int wn = wid & 1;
    const int g  = lane >> 2;
    const int tg = lane & 3;
    const int rowBase = blockIdx.x * 128;

    float c[2][8][4];
    #pragma unroll
    for (int mt = 0; mt < 2; mt++)
        #pragma unroll
        for (int nt = 0; nt < 8; nt++)
            #pragma unroll
            for (int q = 0; q < 4; q++) c[mt][nt][q] = 0.f;

    for (int k0 = 0; k0 < 128; k0 += 32) {
        #pragma unroll
        for (int it = 0; it < 4; it++) {
            int linear = tid + it * 256;
            int r  = linear >> 3;
            int c4 = (linear & 7) * 4;
            float4 v = make_float4(0.f, 0.f, 0.f, 0.f);
            int row = rowBase + r;
            if (row < M) v = *(const float4*)(A + (size_t)row * 128 + k0 + c4);
            As[r][c4 + 0] = f2tf32(v.x);
            As[r][c4 + 1] = f2tf32(v.y);
            As[r][c4 + 2] = f2tf32(v.z);
            As[r][c4 + 3] = f2tf32(v.w);

            int rb  = linear >> 5;
            int cb4 = (linear & 31) * 4;
            float4 bv = *(const float4*)(B + (size_t)(k0 + rb) * 128 + cb4);
            Bs[rb][cb4 + 0] = f2tf32(bv.x);
            Bs[rb][cb4 + 1] = f2tf32(bv.y);
            Bs[rb][cb4 + 2] = f2tf32(bv.z);
            Bs[rb][cb4 + 3] = f2tf32(bv.w);
        }
        __syncthreads();

        #pragma unroll
        for (int ks = 0; ks < 4; ks++) {
            int k8 = ks * 8;
            unsigned a[2][4];
            #pragma unroll
            for (int mt = 0; mt < 2; mt++) {
                int r0 = wm * 32 + mt * 16 + g;
                a[mt][0] = As[r0    ][k8 + tg];
                a[mt][1] = As[r0 + 8][k8 + tg];
                a[mt][2] = As[r0    ][k8 + tg + 4];
                a[mt][3] = As[r0 + 8][k8 + tg + 4];
            }
            unsigned b[8][2];
            #pragma unroll
            for (int nt = 0; nt < 8; nt++) {
                int col = wn * 64 + nt * 8 + g;
                b[nt][0] = Bs[k8 + tg    ][col];
                b[nt][1] = Bs[k8 + tg + 4][col];
            }
            #pragma unroll
            for (int mt = 0; mt < 2; mt++)
                #pragma unroll
                for (int nt = 0; nt < 8; nt++) {
                    asm volatile(
                        "mma.sync.aligned.m16n8k8.row.col.f32.tf32.tf32.f32 "
                        "{%0,%1,%2,%3}, {%4,%5,%6,%7}, {%8,%9}, {%0,%1,%2,%3};"
                        : "+f"(c[mt][nt][0]), "+f"(c[mt][nt][1]),
                          "+f"(c[mt][nt][2]), "+f"(c[mt][nt][3])
                        : "r"(a[mt][0]), "r"(a[mt][1]), "r"(a[mt][2]), "r"(a[mt][3]),
                          "r"(b[nt][0]), "r"(b[nt][1]));
                }
        }
        __syncthreads();
    }

    #pragma unroll
    for (int mt = 0; mt < 2; mt++) {
        int row0 = rowBase + wm * 32 + mt * 16 + g;
        #pragma unroll
        for (int nt = 0; nt < 8; nt++) {
            int col = wn * 64 + nt * 8 + 2 * tg;
            float b0 = bias[col], b1 = bias[col + 1];
            if (row0 < M) {
                float2 o = make_float2(c[mt][nt][0] + b0, c[mt][nt][1] + b1);
                *(float2*)(C + (size_t)row0 * 128 + col) = o;
            }
            int row1 = row0 + 8;
            if (row1 < M) {
                float2 o = make_float2(c[mt][nt][2] + b0, c[mt][nt][3] + b1);
                *(float2*)(C + (size_t)row1 * 128 + col) = o;
            }
        }
    }
}

// ---------------- fused edge-logit + softmax aggregation ----------------
// One warp per destination node. Two edges per inner iteration share each
// fp16 We load: both edges' ea[k] ride in one half2 shfl; each wk LDS.64 is
// consumed by 4 HFMA2 (2 per edge). Crossbar bytes/edge halve vs R14.
__global__ void __launch_bounds__(256) k_fagg(
    const float* __restrict__ ea,
    const float* __restrict__ We, const float* __restrict__ att,
    const float* __restrict__ cb, int E, int N)
{
    __shared__ __align__(16) __half sWe[16 * 128];
    __shared__ __align__(16) float sAtt[128];
    __shared__ float sCb[128];
    int tid = threadIdx.x;
    for (int i = tid; i < 16 * 128; i += blockDim.x) sWe[i] = __float2half(We[i]);
    if (tid < 128) { sAtt[tid] = att[tid]; sCb[tid] = cb[tid]; }
    __syncthreads();

    int lane = tid & 31;
    int c0 = lane * 4;
    int wrp = tid >> 5;
    int stride = gridDim.x * 8;
    float4 av = *(const float4*)(sAtt + c0);

    for (int w = blockIdx.x * 8 + wrp; w < N; w += stride) {
        int beg = g_off[w], end = g_off[w + 1];
        float4 vxr = *(const float4*)(g_xr + (size_t)w * 128 + c0);

        float den = 0.f;
        float a0 = 0.f, a1 = 0.f, a2 = 0.f, a3 = 0.f;

        int j = beg;
        for (; j + 1 < end; j += 2) {
            int2 eA = g_es[j];
            int2 eB = g_es[j + 1];
            const float* pA = (eA.x < E) ? (ea + (size_t)eA.x * 16)
                                         : (g_loop + (size_t)(eA.x - E) * 16);
            const float* pB = (eB.x < E) ? (ea + (size_t)eB.x * 16)
                                         : (g_loop + (size_t)(eB.x - E) * 16);
            unsigned packed = 0;
            if (lane < 16) {
                __half2 hh = __floats2half2_rn(pA[lane], pB[lane]);
                packed = *(unsigned*)&hh;
            }
            float4 vxlA = *(const float4*)(g_xl + (size_t)eA.y * 128 + c0);
            float4 vxlB = *(const float4*)(g_xl + (size_t)eB.y * 128 + c0);

            __half2 zero = __float2half2_rn(0.f);
            __half2 aA01 = zero, aA23 = zero, aB01 = zero, aB23 = zero;
            #pragma unroll
            for (int k = 0; k < 16; k++) {
                unsigned pk = __shfl_sync(0xffffffffu, packed, k);
                __half2 hp = *(__half2*)&pk;
                __half2 aaA = __half2half2(__low2half(hp));
                __half2 aaB = __half2half2(__high2half(hp));
                uint2 wk = *(const uint2*)(sWe + k * 128 + c0);
                __half2 w01 = *(__half2*)&wk.x;
                __half2 w23 = *(__half2*)&wk.y;
                aA01 = __hfma2(aaA, w01, aA01);
                aA23 = __hfma2(aaA, w23, aA23);
                aB01 = __hfma2(aaB, w01, aB01);
                aB23 = __hfma2(aaB, w23, aB23);
            }
            float2 eA01 = __half22float2(aA01);
            float2 eA23 = __half22float2(aA23);
            float2 eB01 = __half22float2(aB01);
            float2 eB23 = __half22float2(aB23);

            // edge A logit
            float m0 = vxlA.x + vxr.x + eA01.x;
            float m1 = vxlA.y + vxr.y + eA01.y;
            float m2 = vxlA.z + vxr.z + eA23.x;
            float m3 = vxlA.w + vxr.w + eA23.y;
            m0 = (m0 > 0.f) ? m0 : 0.2f * m0;
            m1 = (m1 > 0.f) ? m1 : 0.2f * m1;
            m2 = (m2 > 0.f) ? m2 : 0.2f * m2;
            m3 = (m3 > 0.f) ? m3 : 0.2f * m3;
            float pAv = m0 * av.x + m1 * av.y + m2 * av.z + m3 * av.w;
            // edge B logit
            float n0 = vxlB.x + vxr.x + eB01.x;
            float n1 = vxlB.y + vxr.y + eB01.y;
            float n2 = vxlB.z + vxr.z + eB23.x;
            float n3 = vxlB.w + vxr.w + eB23.y;
            n0 = (n0 > 0.f) ? n0 : 0.2f * n0;
            n1 = (n1 > 0.f) ? n1 : 0.2f * n1;
            n2 = (n2 > 0.f) ? n2 : 0.2f * n2;
            n3 = (n3 > 0.f) ? n3 : 0.2f * n3;
            float pBv = n0 * av.x + n1 * av.y + n2 * av.z + n3 * av.w;

            pAv += __shfl_xor_sync(0xffffffffu, pAv, 1);
            pBv += __shfl_xor_sync(0xffffffffu, pBv, 1);
            pAv += __shfl_xor_sync(0xffffffffu, pAv, 2);
            pBv += __shfl_xor_sync(0xffffffffu, pBv, 2);
            pAv += __shfl_xor_sync(0xffffffffu, pAv, 4);
            pBv += __shfl_xor_sync(0xffffffffu, pBv, 4);

            float wA = __expf(pAv);
            float wB = __expf(pBv);
            den += wA + wB;
            a0 += wA * vxlA.x + wB * vxlB.x;
            a1 += wA * vxlA.y + wB * vxlB.y;
            a2 += wA * vxlA.z + wB * vxlB.z;
            a3 += wA * vxlA.w + wB * vxlB.w;
        }
        // odd tail
        if (j < end) {
            int2 es = g_es[j];
            const float* eav = (es.x < E) ? (ea + (size_t)es.x * 16)
                                          : (g_loop + (size_t)(es.x - E) * 16);
            float myea = (lane < 16) ? eav[lane] : 0.f;
            float4 vxl = *(const float4*)(g_xl + (size_t)es.y * 128 + c0);

            __half2 acc01 = __float2half2_rn(0.f);
            __half2 acc23 = __float2half2_rn(0.f);
            #pragma unroll
            for (int k = 0; k < 16; k++) {
                float aa = __shfl_sync(0xffffffffu, myea, k);
                __half2 aah = __float2half2_rn(aa);
                uint2 wk = *(const uint2*)(sWe + k * 128 + c0);
                acc01 = __hfma2(aah, *(__half2*)&wk.x, acc01);
                acc23 = __hfma2(aah, *(__half2*)&wk.y, acc23);
            }
            float2 e01 = __half22float2(acc01);
            float2 e23 = __half22float2(acc23);

            float m0 = vxl.x + vxr.x + e01.x;
            float m1 = vxl.y + vxr.y + e01.y;
            float m2 = vxl.z + vxr.z + e23.x;
            float m3 = vxl.w + vxr.w + e23.y;
            m0 = (m0 > 0.f) ? m0 : 0.2f * m0;
            m1 = (m1 > 0.f) ? m1 : 0.2f * m1;
            m2 = (m2 > 0.f) ? m2 : 0.2f * m2;
            m3 = (m3 > 0.f) ? m3 : 0.2f * m3;
            float p = m0 * av.x + m1 * av.y + m2 * av.z + m3 * av.w;
            p += __shfl_xor_sync(0xffffffffu, p, 1);
            p += __shfl_xor_sync(0xffffffffu, p, 2);
            p += __shfl_xor_sync(0xffffffffu, p, 4);

            float wgt = __expf(p);
            den += wgt;
            a0 += wgt * vxl.x;
            a1 += wgt * vxl.y;
            a2 += wgt * vxl.z;
            a3 += wgt * vxl.w;
        }

        float inv = 1.f / den;
        float o0 = a0 * inv + sCb[c0 + 0];
        float o1 = a1 * inv + sCb[c0 + 1];
        float o2 = a2 * inv + sCb[c0 + 2];
        float o3 = a3 * inv + sCb[c0 + 3];
        o0 = (o0 > 0.f) ? o0 : expm1f(o0);
        o1 = (o1 > 0.f) ? o1 : expm1f(o1);
        o2 = (o2 > 0.f) ? o2 : expm1f(o2);
        o3 = (o3 > 0.f) ? o3 : expm1f(o3);
        *(float4*)(g_h + (size_t)w * 128 + c0) = make_float4(o0, o1, o2, o3);
    }
}

// ---------------- LayerNorm + MLP head (one warp per node, grid-stride) ----------------
__global__ void __launch_bounds__(256) k_head(
    const float* __restrict__ ln_g, const float* __restrict__ ln_b,
    const float* __restrict__ h1w, const float* __restrict__ h1b,
    const float* __restrict__ h2w, const float* __restrict__ h2b,
    float* __restrict__ out, int N)
{
    __shared__ __align__(16) float sW1[128 * 64];
    __shared__ float sg[128], sb[128], sb1[64], sW2[64 * 3], sb2[4];
    __shared__ __align__(16) float srow[8][128];
    int tid = threadIdx.x;
    for (int i = tid; i < 128 * 64; i += blockDim.x) sW1[i] = h1w[i];
    if (tid < 128) { sg[tid] = ln_g[tid]; sb[tid] = ln_b[tid]; }
    if (tid < 64)  sb1[tid] = h1b[tid];
    if (tid < 192) sW2[tid] = h2w[tid];
    if (tid < 3)   sb2[tid] = h2b[tid];
    __syncthreads();

    int wrp = tid >> 5;
    int lane = tid & 31;
    int c0 = lane * 4;
    int stride = gridDim.x * 8;

    for (int w = blockIdx.x * 8 + wrp; w < N; w += stride) {
        float4 hv = *(const float4*)(g_h + (size_t)w * 128 + c0);
        float sum = hv.x + hv.y + hv.z + hv.w;
        #pragma unroll
        for (int o = 16; o >= 1; o >>= 1) sum += __shfl_xor_sync(0xffffffffu, sum, o);
        float mu = sum * (1.f / 128.f);
        float dx = hv.x - mu, dy = hv.y - mu, dz = hv.z - mu, dw = hv.w - mu;
        float sq = dx * dx + dy * dy + dz * dz + dw * dw;
        #pragma unroll
        for (int o = 16; o >= 1; o >>= 1) sq += __shfl_xor_sync(0xffffffffu, sq, o);
        float rstd = rsqrtf(sq * (1.f / 128.f) + 1e-5f);
        srow[wrp][c0 + 0] = dx * rstd * sg[c0 + 0] + sb[c0 + 0];
        srow[wrp][c0 + 1] = dy * rstd * sg[c0 + 1] + sb[c0 + 1];
        srow[wrp][c0 + 2] = dz * rstd * sg[c0 + 2] + sb[c0 + 2];
        srow[wrp][c0 + 3] = dw * rstd * sg[c0 + 3] + sb[c0 + 3];
        __syncwarp();

        const float2* W1v = (const float2*)sW1;
        float a0 = sb1[2 * lane], a1 = sb1[2 * lane + 1];
        #pragma unroll 8
        for (int k = 0; k < 128; k++) {
            float r = srow[wrp][k];
            float2 wvv = W1v[k * 32 + lane];
            a0 += r * wvv.x;
            a1 += r * wvv.y;
        }
        a0 = fmaxf(a0, 0.f);
        a1 = fmaxf(a1, 0.f);
        float p0 = a0 * sW2[(2 * lane) * 3 + 0] + a1 * sW2[(2 * lane + 1) * 3 + 0];
        float p1 = a0 * sW2[(2 * lane) * 3 + 1] + a1 * sW2[(2 * lane + 1) * 3 + 1];
        float p2 = a0 * sW2[(2 * lane) * 3 + 2] + a1 * sW2[(2 * lane + 1) * 3 + 2];
        #pragma unroll
        for (int o = 16; o >= 1; o >>= 1) {
            p0 += __shfl_xor_sync(0xffffffffu, p0, o);
            p1 += __shfl_xor_sync(0xffffffffu, p1, o);
            p2 += __shfl_xor_sync(0xffffffffu, p2, o);
        }
        if (lane == 0) {
            out[(size_t)w * 3 + 0] = p0 + sb2[0];
            out[(size_t)w * 3 + 1] = p1 + sb2[1];
            out[(size_t)w * 3 + 2] = p2 + sb2[2];
        }
        __syncwarp();
    }
}

// ---------------- launch ----------------
extern "C" void kernel_launch(void* const* d_in, const int* in_sizes, int n_in,
                              void* d_out, int out_size)
{
    const float* x    = (const float*)d_in[0];
    const void*  ei   = d_in[1];
    const float* ea   = (const float*)d_in[2];
    const float* in_w = (const float*)d_in[3];
    const float* in_b = (const float*)d_in[4];
    const float* Wl   = (const float*)d_in[5];
    const float* bl   = (const float*)d_in[6];
    const float* Wr   = (const float*)d_in[7];
    const float* br   = (const float*)d_in[8];
    const float* We   = (const float*)d_in[9];
    const float* att  = (const float*)d_in[10];
    const float* cb   = (const float*)d_in[11];
    const float* ln_g = (const float*)d_in[12];
    const float* ln_b = (const float*)d_in[13];
    const float* h1w  = (const float*)d_in[14];
    const float* h1b  = (const float*)d_in[15];
    const float* h2w  = (const float*)d_in[16];
    const float* h2b  = (const float*)d_in[17];
    float* out = (float*)d_out;

    int N = in_sizes[0] / 128;
    int E = in_sizes[2] / 16;
    int EN = E + N;
    int nb1024 = (N + 1023) / 1024;

    k_detect<<<1, 256>>>((const int*)ei);
    k_zero<<<(N + 255) / 256, 256>>>(N);
    k_hist<<<(E + 255) / 256, 256>>>(ei, E);
    k_scan1<<<nb1024, 1024>>>(N);
    k_scan2<<<1, 128>>>(nb1024);
    k_scan3<<<(N + 1023) / 1024, 1024>>>(N);
    k_fill<<<(EN + 255) / 256, 256>>>(ei, E, EN);
    k_loopattr<<<(N + 7) / 8, 256>>>(ea, E, N);
    k_combine<<<dim3(128, 2), 128>>>(in_w, in_b, Wl, bl, Wr, br);

    int gb = (N + 127) / 128;
    // layer 0: xl = x @ (in_w@Wl0), xr = x @ (in_w@Wr0)  (composed weights)
    mma_gemm<<<dim3(gb, 2), 256>>>(x,
                                   nullptr, nullptr, /*bsel=*/0, /*dst=*/1,
                                   nullptr, nullptr, /*bsel=*/1, /*dst=*/2, N);
    k_fagg<<<(N + 7) / 8, 256>>>(ea, We, att, cb, E, N);

    // layer 1: from g_h
    mma_gemm<<<dim3(gb, 2), 256>>>(nullptr,
                                   Wl + (size_t)128 * 128, bl + 128, -1, /*dst=*/1,
                                   Wr + (size_t)128 * 128, br + 128, -1, /*dst=*/2, N);
    k_fagg<<<(N + 7) / 8, 256>>>(ea, We + (size_t)16 * 128, att + 128, cb + 128, E, N);

    k_head<<<592, 256>>>(ln_g, ln_b, h1w, h1b, h2w, h2b, out, N);
}